// round 14
// baseline (speedup 1.0000x reference)
#include <cuda_runtime.h>
#include <math.h>
#include <stdint.h>

#define NPTS 200000
#define TVSEG 1382400           // B*GZ2*GY2*GX2 = 2*16*180*240
#define NSEG_TOTAL 1634400      // 1382400 + 172800 + 57600 + 21600
#define SEGCAP 200704           // 784*256, >= max touched segs per scale

typedef unsigned long long u64;

// packed fp32x2 (Blackwell): d = a*b + d on two fp32 lanes
#define FFMA2(acc, a, b) \
    asm("fma.rn.f32x2 %0, %1, %2, %0;" : "+l"(acc) : "l"(a), "l"(b))
#define PACK2(d, f) \
    asm("mov.b64 %0, {%1, %1};" : "=l"(d) : "f"(f))
#define PACKLH(d, lo, hi) \
    asm("mov.b64 %0, {%1, %2};" : "=l"(d) : "f"(lo), "f"(hi))
#define UNPK(lo, hi, u) \
    asm("mov.b64 {%0, %1}, %2;" : "=f"(lo), "=f"(hi) : "l"(u))

// ---------------- scratch (device globals; no allocation allowed) ----------
__device__ float g_reduced[NPTS * 64];                  // 51 MB
__device__ float g_segsum[(size_t)NSEG_TOTAL * 64];     // 418 MB (touched-only init)
__device__ float g_segcnt[NSEG_TOTAL];
__device__ int   g_lin[NPTS * 4];
__device__ int   g_segidx[NSEG_TOTAL];                  // lin -> att slot (init -1)
__device__ int   g_seglist[4 * SEGCAP];                 // compact touched lists
__device__ int   g_cnt4[4];
__device__ int   g_pidx[NPTS * 4];                      // per (point,scale) att slot
__device__ float g_att[(size_t)4 * SEGCAP * 32];        // 103 MB
__device__ float g_proj[NPTS * 64];
__device__ float g_tv[(size_t)TVSEG * 64];              // 354 MB (touched-only init)
__device__ int   g_lin2[NPTS];
__device__ unsigned char g_flag[TVSEG];

// ---------------- k0a: thread per (point,scale): lin + claim ticket --------
__global__ void __launch_bounds__(256) k0a_claim(const int* __restrict__ coords)
{
    int idx = blockIdx.x * 256 + threadIdx.x;    // 800000 exactly
    int n = idx >> 2, j = idx & 3;

    int4 c = reinterpret_cast<const int4*>(coords)[n];
    int ps = (j == 0) ? 2 : (j == 1) ? 4 : (j == 2) ? 6 : 8;
    int dx = (j == 0) ? 240 : (j == 1) ? 120 : (j == 2) ? 80 : 60;
    int dy = (j == 0) ? 180 : (j == 1) ? 90 : (j == 2) ? 60 : 45;
    int dz = (j == 0) ? 16 : (j == 1) ? 8 : (j == 2) ? 6 : 4;
    int off = (j == 0) ? 0 : (j == 1) ? 1382400 : (j == 2) ? 1555200 : 1612800;

    int lin = ((c.x * dx + c.y / ps) * dy + c.z / ps) * dz + c.w / ps + off;
    g_lin[idx] = lin;

    if (atomicCAS(&g_segidx[lin], -1, 0x40000000) == -1) {
        int t = atomicAdd(&g_cnt4[j], 1);
        g_seglist[j * SEGCAP + t] = lin;
        g_segidx[lin] = j * SEGCAP + t;
    }
}

// ---------------- k0b: zero claimed segs + pidx resolve + tv sentinel ------
__global__ void __launch_bounds__(256) k0b_zero(const int* __restrict__ bxyz,
                                                float* __restrict__ out)
{
    int T = blockIdx.x * 256 + threadIdx.x;      // 8 threads per slot
    // side job 1: resolve g_pidx for k2_pt (removes its 2-hop load chain)
    if (T < NPTS * 4) g_pidx[T] = g_segidx[g_lin[T]];

    // side job 2 (former k3pre): sentinel-init touched tv segs, flags, lin2
    if (T < NPTS * 8) {
        int p = T >> 3, q = T & 7;
        int4 b = reinterpret_cast<const int4*>(bxyz)[p];
        int lin2 = ((b.x * 16 + b.w) * 180 + b.z) * 240 + b.y;
        uint4 s = make_uint4(0xFFFFFFFFu, 0xFFFFFFFFu, 0xFFFFFFFFu, 0xFFFFFFFFu);
        uint4* tv = reinterpret_cast<uint4*>(g_tv + (size_t)lin2 * 64);
        tv[2 * q]     = s;
        tv[2 * q + 1] = s;
        if (q == 0) {
            g_flag[lin2] = 1;
            g_lin2[p] = lin2;
            out[(size_t)NPTS * 64 + (size_t)TVSEG * 64 + p] = (float)lin2;
        }
    }

    int slot = T >> 3, q = T & 7;
    int j = slot / SEGCAP, i = slot - j * SEGCAP;
    if (i >= g_cnt4[j]) return;
    int lin = g_seglist[slot];
    float4 z4 = make_float4(0.f, 0.f, 0.f, 0.f);
    float4* dst = reinterpret_cast<float4*>(g_segsum + (size_t)lin * 64) + q * 2;
    dst[0] = z4;
    dst[1] = z4;
    if (q == 0) g_segcnt[lin] = 0.f;
}

// ---------------- k1: tile-staged reduce GEMM + warp-coop scatter ----------
// dyn smem floats: sW [64][64] 0..4096 | sb 4096..4160 | sx [256][65] 4160..
#define K1PAD 65
#define K1_SMEM ((4160 + 256 * K1PAD) * 4)
__global__ void __launch_bounds__(256, 3) k1_reduce(
    const float* __restrict__ input,
    const float* __restrict__ W_red, const float* __restrict__ b_red)
{
    extern __shared__ float s1[];
    float* sW = s1;
    float* sb = s1 + 4096;
    float* sx = s1 + 4160;
    const int tid = threadIdx.x;

    for (int i = tid; i < 4096; i += 256) sW[i] = W_red[i];
    if (tid < 64) sb[tid] = b_red[tid];

    const int pbase = blockIdx.x * 256;
    const float4* in4 = reinterpret_cast<const float4*>(input);
    #pragma unroll
    for (int i = 0; i < 16; ++i) {
        int e4 = i * 256 + tid;
        int pt = e4 >> 4, q = e4 & 15;
        if (pbase + pt < NPTS) {
            float4 v = in4[(size_t)(pbase + pt) * 16 + q];
            float* d = sx + pt * K1PAD + q * 4;
            d[0] = v.x; d[1] = v.y; d[2] = v.z; d[3] = v.w;
        }
    }
    __syncthreads();

    // GEMM: thread-per-point, f32x2 channel-packed, weights broadcast LDS
    {
        u64 acc[32];
        const u64* bp = reinterpret_cast<const u64*>(sb);
        #pragma unroll
        for (int i = 0; i < 32; ++i) acc[i] = bp[i];
        const ulonglong2* Wb = reinterpret_cast<const ulonglong2*>(sW);
        float* row = sx + tid * K1PAD;
        #pragma unroll 8
        for (int k = 0; k < 64; ++k) {
            u64 xp; PACK2(xp, row[k]);
            const ulonglong2* W = Wb + k * 16;
            #pragma unroll
            for (int i = 0; i < 16; ++i) {
                ulonglong2 wv = W[i];
                FFMA2(acc[2 * i],     xp, wv.x);
                FFMA2(acc[2 * i + 1], xp, wv.y);
            }
        }
        // relu + writeback to own row (x no longer needed)
        #pragma unroll
        for (int i = 0; i < 32; ++i) {
            float lo, hi; UNPK(lo, hi, acc[i]);
            row[2 * i]     = fmaxf(lo, 0.f);
            row[2 * i + 1] = fmaxf(hi, 0.f);
        }
    }
    __syncthreads();

    // warp-cooperative scatter: warp w handles points [pbase+w*32, +32)
    // NOTE: sx rows are at ODD float offsets (K1PAD=65) — scalar LDS only.
    const int wid = tid >> 5, lane = tid & 31;
    #pragma unroll 1
    for (int pp = 0; pp < 32; ++pp) {
        int pl = wid * 32 + pp;
        int p = pbase + pl;
        if (p >= NPTS) break;
        float v0 = sx[pl * K1PAD + 2 * lane];
        float v1 = sx[pl * K1PAD + 2 * lane + 1];
        reinterpret_cast<float2*>(g_reduced)[(size_t)p * 32 + lane]
            = make_float2(v0, v1);
        int4 L = reinterpret_cast<const int4*>(g_lin)[p];
        int lins[4] = {L.x, L.y, L.z, L.w};
        #pragma unroll
        for (int j = 0; j < 4; ++j) {
            float* addr = g_segsum + (size_t)lins[j] * 64 + 2 * lane;
            asm volatile("red.global.add.v2.f32 [%0], {%1, %2};"
                         :: "l"(addr), "f"(v0), "f"(v1) : "memory");
            if (lane == 0) atomicAdd(&g_segcnt[lins[j]], 1.0f);
        }
    }
}

// ---------------- k2_seg: per touched segment, att = relu(mean @ flW + b) --
// direct gmem loads (measured best); per-scale weights only (8 KB)
__global__ void __launch_bounds__(256, 4) k2_seg(
    const float* __restrict__ flW, const float* __restrict__ flb)
{
    __shared__ __align__(16) float sW[2048];
    __shared__ __align__(16) float sb[32];
    const int tid = threadIdx.x;
    const int j = blockIdx.x / 784;
    const int base = (blockIdx.x % 784) * 256;

    for (int i = tid; i < 2048; i += 256) sW[i] = flW[j * 2048 + i];
    if (tid < 32) sb[tid] = flb[j * 32 + tid];
    __syncthreads();

    const int i = base + tid;
    if (i >= g_cnt4[j]) return;
    const int lin = g_seglist[j * SEGCAP + i];

    float inv = 1.f / fmaxf(g_segcnt[lin], 1.f);

    u64 acc[16];
    {
        const u64* bp = reinterpret_cast<const u64*>(sb);
        #pragma unroll
        for (int q = 0; q < 16; ++q) acc[q] = bp[q];
    }
    const ulonglong2* Wb = reinterpret_cast<const ulonglong2*>(sW);
    const float4* src = reinterpret_cast<const float4*>(g_segsum + (size_t)lin * 64);

    #pragma unroll 1
    for (int kc = 0; kc < 4; ++kc) {
        float4 fk4[4];
        #pragma unroll
        for (int q = 0; q < 4; ++q) fk4[q] = __ldcs(&src[kc * 4 + q]);
        #pragma unroll
        for (int k = 0; k < 16; ++k) {
            float4 v = fk4[k >> 2];
            float xs = ((k & 3) == 0) ? v.x : ((k & 3) == 1) ? v.y
                       : ((k & 3) == 2) ? v.z : v.w;
            xs *= inv;
            u64 xp; PACK2(xp, xs);
            const ulonglong2* W = Wb + (kc * 16 + k) * 8;
            #pragma unroll
            for (int q = 0; q < 8; ++q) {
                ulonglong2 wv = W[q];
                FFMA2(acc[2 * q],     xp, wv.x);
                FFMA2(acc[2 * q + 1], xp, wv.y);
            }
        }
    }
    float4* dst = reinterpret_cast<float4*>(g_att + (size_t)(j * SEGCAP + i) * 32);
    #pragma unroll
    for (int q = 0; q < 8; ++q) {
        float l0, h0, l1, h1;
        UNPK(l0, h0, acc[2 * q]);
        UNPK(l1, h1, acc[2 * q + 1]);
        dst[q] = make_float4(fmaxf(l0, 0.f), fmaxf(h0, 0.f),
                             fmaxf(l1, 0.f), fmaxf(h1, 0.f));
    }
}

// ---------------- k2_pt: per-point chain, f32x2 channel-packed -------------
#define K2T 256
// SMEM float offsets:
#define OFFP_FCW   0        // [32][32]     1024
#define OFFP_FCSW  1024     // [4][32][32]  4096
#define OFFP_FCSB  5120     // 128
#define OFFP_OUTW  5248     // [32][64]     2048
#define OFFP_LO1   7296     // [128][64]    8192
#define OFFP_LO2   15488    // [64][64]     4096
#define OFFP_LOB   19584    // 64
#define OFFP_X     19648    // scratch [32][256]  8192
#define K2PT_SMEM ((19648 + 32 * K2T) * 4)

__global__ void __launch_bounds__(K2T, 2) k2_pt(
    const float* __restrict__ fcW, const float* __restrict__ fcsW,
    const float* __restrict__ fcsb, const float* __restrict__ outW,
    const float* __restrict__ lo1, const float* __restrict__ lo2,
    const float* __restrict__ lob)
{
    extern __shared__ float sm[];
    const int tid = threadIdx.x;

    for (int i = tid; i < 1024; i += K2T) sm[OFFP_FCW + i]  = fcW[i];
    for (int i = tid; i < 4096; i += K2T) sm[OFFP_FCSW + i] = fcsW[i];
    for (int i = tid; i < 128;  i += K2T) sm[OFFP_FCSB + i] = fcsb[i];
    for (int i = tid; i < 2048; i += K2T) sm[OFFP_OUTW + i] = outW[i];
    for (int i = tid; i < 8192; i += K2T) sm[OFFP_LO1 + i]  = lo1[i];
    for (int i = tid; i < 4096; i += K2T) sm[OFFP_LO2 + i]  = lo2[i];
    if (tid < 64) sm[OFFP_LOB + tid] = lob[tid];
    __syncthreads();

    const int n = blockIdx.x * K2T + tid;
    if (n >= NPTS) return;
    float* s_x = sm + OFFP_X;

    int4 pid = *reinterpret_cast<const int4*>(g_pidx + n * 4);
    int idx4[4] = {pid.x, pid.y, pid.z, pid.w};

    // ===== P1: featS = sum_j att_j (regs) =================================
    float featS[32];
    #pragma unroll
    for (int c = 0; c < 32; ++c) featS[c] = 0.f;
    #pragma unroll 2
    for (int j = 0; j < 4; ++j) {
        const float4* sf = reinterpret_cast<const float4*>(
            g_att + (size_t)idx4[j] * 32);
        #pragma unroll
        for (int i = 0; i < 8; ++i) {
            float4 v = sf[i];
            featS[4 * i + 0] += v.x; featS[4 * i + 1] += v.y;
            featS[4 * i + 2] += v.z; featS[4 * i + 3] += v.w;
        }
    }

    // ===== P2: z = relu(featS @ fcW), z kept packed (u64 pairs) ===========
    u64 zp[16];
    {
        #pragma unroll
        for (int i = 0; i < 16; ++i) zp[i] = 0ull;
        const ulonglong2* Wf = reinterpret_cast<const ulonglong2*>(sm + OFFP_FCW);
        #pragma unroll
        for (int k = 0; k < 32; ++k) {
            u64 xp; PACK2(xp, featS[k]);
            const ulonglong2* W = Wf + k * 8;
            #pragma unroll
            for (int i = 0; i < 8; ++i) {
                ulonglong2 wv = W[i];
                FFMA2(zp[2 * i],     xp, wv.x);
                FFMA2(zp[2 * i + 1], xp, wv.y);
            }
        }
        #pragma unroll
        for (int i = 0; i < 16; ++i) {
            float lo, hi; UNPK(lo, hi, zp[i]);
            lo = fmaxf(lo, 0.f); hi = fmaxf(hi, 0.f);
            PACKLH(zp[i], lo, hi);
        }
    }

    // ===== P3: fp = sum_j att_j * sigmoid(z @ fcsW_j + fcsb_j) ============
    float fp[32];
    #pragma unroll
    for (int c = 0; c < 32; ++c) fp[c] = 0.f;
    #pragma unroll 1
    for (int j = 0; j < 4; ++j) {
        u64 acc[16];
        {
            const u64* bp = reinterpret_cast<const u64*>(sm + OFFP_FCSB + j * 32);
            #pragma unroll
            for (int i = 0; i < 16; ++i) acc[i] = bp[i];
        }
        const ulonglong2* Wj = reinterpret_cast<const ulonglong2*>(sm + OFFP_FCSW)
                               + (size_t)j * 32 * 8;
        #pragma unroll
        for (int kp = 0; kp < 16; ++kp) {
            float zl, zh; UNPK(zl, zh, zp[kp]);
            u64 xp0; PACK2(xp0, zl);
            const ulonglong2* W = Wj + (2 * kp) * 8;
            #pragma unroll
            for (int i = 0; i < 8; ++i) {
                ulonglong2 wv = W[i];
                FFMA2(acc[2 * i],     xp0, wv.x);
                FFMA2(acc[2 * i + 1], xp0, wv.y);
            }
            u64 xp1; PACK2(xp1, zh);
            W = Wj + (2 * kp + 1) * 8;
            #pragma unroll
            for (int i = 0; i < 8; ++i) {
                ulonglong2 wv = W[i];
                FFMA2(acc[2 * i],     xp1, wv.x);
                FFMA2(acc[2 * i + 1], xp1, wv.y);
            }
        }
        const float4* sfsrc = reinterpret_cast<const float4*>(
            g_att + (size_t)idx4[j] * 32);
        #pragma unroll
        for (int i = 0; i < 8; ++i) {
            float4 sv = sfsrc[i];
            float l0, h0, l1, h1;
            UNPK(l0, h0, acc[2 * i]);
            UNPK(l1, h1, acc[2 * i + 1]);
            float a0 = __fdividef(1.f, 1.f + __expf(-l0));
            float a1 = __fdividef(1.f, 1.f + __expf(-h0));
            float a2 = __fdividef(1.f, 1.f + __expf(-l1));
            float a3 = __fdividef(1.f, 1.f + __expf(-h1));
            fp[4 * i + 0] = fmaf(sv.x, a0, fp[4 * i + 0]);
            fp[4 * i + 1] = fmaf(sv.y, a1, fp[4 * i + 1]);
            fp[4 * i + 2] = fmaf(sv.z, a2, fp[4 * i + 2]);
            fp[4 * i + 3] = fmaf(sv.w, a3, fp[4 * i + 3]);
        }
    }

    // ===== P4: fused = fp @ outW (packed); low half -> scratch ============
    u64 facc[32];
    {
        #pragma unroll
        for (int i = 0; i < 32; ++i) facc[i] = 0ull;
        const ulonglong2* Wo = reinterpret_cast<const ulonglong2*>(sm + OFFP_OUTW);
        #pragma unroll
        for (int k = 0; k < 32; ++k) {
            u64 xp; PACK2(xp, fp[k]);
            const ulonglong2* W = Wo + k * 16;
            #pragma unroll
            for (int i = 0; i < 16; ++i) {
                ulonglong2 wv = W[i];
                FFMA2(facc[2 * i],     xp, wv.x);
                FFMA2(facc[2 * i + 1], xp, wv.y);
            }
        }
        // stage fused channels 0..31 (facc[0..15]) to scratch rows 0..31
        #pragma unroll
        for (int i = 0; i < 16; ++i) {
            float lo, hi; UNPK(lo, hi, facc[i]);
            s_x[(2 * i) * K2T + tid]     = lo;
            s_x[(2 * i + 1) * K2T + tid] = hi;
        }
    }

    // ===== P5: h = relu([reduced, fused] @ lo1) (packed accs) =============
    float h[64];
    {
        u64 hacc[32];
        #pragma unroll
        for (int i = 0; i < 32; ++i) hacc[i] = 0ull;
        const ulonglong2* Wl = reinterpret_cast<const ulonglong2*>(sm + OFFP_LO1);
        const float4* rsrc = reinterpret_cast<const float4*>(
            g_reduced + (size_t)n * 64);
        // (a) reduced, k = 0..63  (unroll 2 -> 2 float4 loads in flight)
        #pragma unroll 2
        for (int k4 = 0; k4 < 16; ++k4) {
            float4 r = rsrc[k4];
            #pragma unroll
            for (int kk = 0; kk < 4; ++kk) {
                float xs = (kk == 0) ? r.x : (kk == 1) ? r.y : (kk == 2) ? r.z : r.w;
                u64 xp; PACK2(xp, xs);
                const ulonglong2* W = Wl + (k4 * 4 + kk) * 16;
                #pragma unroll
                for (int i = 0; i < 16; ++i) {
                    ulonglong2 wv = W[i];
                    FFMA2(hacc[2 * i],     xp, wv.x);
                    FFMA2(hacc[2 * i + 1], xp, wv.y);
                }
            }
        }
        // (b) fused low from scratch, k = 64..95
        #pragma unroll 2
        for (int k = 0; k < 32; ++k) {
            float xs = s_x[k * K2T + tid];
            u64 xp; PACK2(xp, xs);
            const ulonglong2* W = Wl + (64 + k) * 16;
            #pragma unroll
            for (int i = 0; i < 16; ++i) {
                ulonglong2 wv = W[i];
                FFMA2(hacc[2 * i],     xp, wv.x);
                FFMA2(hacc[2 * i + 1], xp, wv.y);
            }
        }
        // (c) fused high from regs, k = 96..127
        #pragma unroll
        for (int kp = 0; kp < 16; ++kp) {
            float f0, f1; UNPK(f0, f1, facc[16 + kp]);
            u64 xp0; PACK2(xp0, f0);
            const ulonglong2* W = Wl + (96 + 2 * kp) * 16;
            #pragma unroll
            for (int i = 0; i < 16; ++i) {
                ulonglong2 wv = W[i];
                FFMA2(hacc[2 * i],     xp0, wv.x);
                FFMA2(hacc[2 * i + 1], xp0, wv.y);
            }
            u64 xp1; PACK2(xp1, f1);
            W = Wl + (96 + 2 * kp + 1) * 16;
            #pragma unroll
            for (int i = 0; i < 16; ++i) {
                ulonglong2 wv = W[i];
                FFMA2(hacc[2 * i],     xp1, wv.x);
                FFMA2(hacc[2 * i + 1], xp1, wv.y);
            }
        }
        #pragma unroll
        for (int i = 0; i < 32; ++i) {
            float lo, hi; UNPK(lo, hi, hacc[i]);
            h[2 * i]     = fmaxf(lo, 0.f);
            h[2 * i + 1] = fmaxf(hi, 0.f);
        }
    }

    // ===== P6: proj = h @ lo2 + lob, in two 32-ch halves ==================
    float4* pdst = reinterpret_cast<float4*>(g_proj + (size_t)n * 64);
    const ulonglong2* W2 = reinterpret_cast<const ulonglong2*>(sm + OFFP_LO2);
    #pragma unroll 1
    for (int s = 0; s < 2; ++s) {
        u64 pa[16];
        {
            const u64* bp = reinterpret_cast<const u64*>(sm + OFFP_LOB) + s * 16;
            #pragma unroll
            for (int i = 0; i < 16; ++i) pa[i] = bp[i];
        }
        #pragma unroll
        for (int k = 0; k < 64; ++k) {
            u64 xp; PACK2(xp, h[k]);
            const ulonglong2* W = W2 + k * 16 + s * 8;
            #pragma unroll
            for (int i = 0; i < 8; ++i) {
                ulonglong2 wv = W[i];
                FFMA2(pa[2 * i],     xp, wv.x);
                FFMA2(pa[2 * i + 1], xp, wv.y);
            }
        }
        #pragma unroll
        for (int q = 0; q < 8; ++q) {
            float l0, h0, l1, h1;
            UNPK(l0, h0, pa[2 * q]);
            UNPK(l1, h1, pa[2 * q + 1]);
            pdst[s * 8 + q] = make_float4(l0, h0, l1, h1);
        }
    }
}

// ---------------- k3: gather by inv + atomic segment-max -------------------
__device__ __forceinline__ void atomicMaxFloat(float* addr, float v)
{
    if (v >= 0.f) atomicMax((int*)addr, __float_as_int(v));
    else          atomicMin((unsigned int*)addr, __float_as_uint(v));
}

__global__ void __launch_bounds__(256) k3_scatter(const int* __restrict__ inv,
                                                  float* __restrict__ out)
{
    int idx = blockIdx.x * 256 + threadIdx.x;
    int n = idx >> 6, c = idx & 63;
    int src = inv[n];
    float v = g_proj[src * 64 + c];
    __stcs(&out[idx], v);                // streaming: out not re-read
    int lin2 = g_lin2[n];
    atomicMaxFloat(&g_tv[(size_t)lin2 * 64 + c], v);
}

// ---------------- k4: finalize tv -> out (flag-gated) ----------------------
__global__ void __launch_bounds__(256) k4_final(float* __restrict__ out)
{
    size_t idx = (size_t)blockIdx.x * 256 + threadIdx.x;   // float4 units
    size_t seg = idx >> 4;
    float4 v = make_float4(0.f, 0.f, 0.f, 0.f);
    if (g_flag[seg])
        v = __ldcs(reinterpret_cast<const float4*>(g_tv) + idx);
    __stcs(reinterpret_cast<float4*>(out + (size_t)NPTS * 64) + idx, v);
}

// ---------------- launch ---------------------------------------------------
extern "C" void kernel_launch(void* const* d_in, const int* in_sizes, int n_in,
                              void* d_out, int out_size)
{
    const float* input     = (const float*)d_in[0];
    const int*   coords    = (const int*)  d_in[1];
    const int*   inv       = (const int*)  d_in[2];
    const int*   bxyz      = (const int*)  d_in[3];
    const float* W_red     = (const float*)d_in[4];
    const float* b_red     = (const float*)d_in[5];
    const float* fc_list_W = (const float*)d_in[6];
    const float* fc_list_b = (const float*)d_in[7];
    const float* fcs_W     = (const float*)d_in[8];
    const float* fcs_b     = (const float*)d_in[9];
    const float* fc_W      = (const float*)d_in[10];
    const float* out_fc_W  = (const float*)d_in[11];
    const float* lo_W1     = (const float*)d_in[12];
    const float* lo_W2     = (const float*)d_in[13];
    const float* lo_b2     = (const float*)d_in[14];
    float* out = (float*)d_out;

    void* p;
    cudaGetSymbolAddress(&p, g_flag);
    cudaMemsetAsync(p, 0, TVSEG);
    cudaGetSymbolAddress(&p, g_segidx);
    cudaMemsetAsync(p, 0xFF, NSEG_TOTAL * sizeof(int));   // -1
    cudaGetSymbolAddress(&p, g_cnt4);
    cudaMemsetAsync(p, 0, 4 * sizeof(int));

    cudaFuncSetAttribute(k1_reduce, cudaFuncAttributeMaxDynamicSharedMemorySize,
                         K1_SMEM);
    cudaFuncSetAttribute(k2_pt, cudaFuncAttributeMaxDynamicSharedMemorySize,
                         K2PT_SMEM);

    k0a_claim<<<3125, 256>>>(coords);                       // 800k threads
    k0b_zero<<<(4 * SEGCAP * 8) / 256, 256>>>(bxyz, out);   // zero + pidx + tv
    k1_reduce<<<782, 256, K1_SMEM>>>(input, W_red, b_red);
    k2_seg<<<4 * 784, 256>>>(fc_list_W, fc_list_b);
    k2_pt<<<(NPTS + K2T - 1) / K2T, K2T, K2PT_SMEM>>>(fc_W, fcs_W, fcs_b,
                                                      out_fc_W, lo_W1, lo_W2,
                                                      lo_b2);
    k3_scatter<<<50000, 256>>>(inv, out);
    k4_final<<<86400, 256>>>(out);
}

// round 15
// speedup vs baseline: 1.0622x; 1.0622x over previous
#include <cuda_runtime.h>
#include <math.h>
#include <stdint.h>

#define NPTS 200000
#define TVSEG 1382400           // B*GZ2*GY2*GX2 = 2*16*180*240
#define NSEG_TOTAL 1634400      // 1382400 + 172800 + 57600 + 21600
#define SEGCAP 200704           // 784*256, >= max touched segs per scale

typedef unsigned long long u64;

// packed fp32x2 (Blackwell): d = a*b + d on two fp32 lanes
#define FFMA2(acc, a, b) \
    asm("fma.rn.f32x2 %0, %1, %2, %0;" : "+l"(acc) : "l"(a), "l"(b))
#define PACK2(d, f) \
    asm("mov.b64 %0, {%1, %1};" : "=l"(d) : "f"(f))
#define PACKLH(d, lo, hi) \
    asm("mov.b64 %0, {%1, %2};" : "=l"(d) : "f"(lo), "f"(hi))
#define UNPK(lo, hi, u) \
    asm("mov.b64 {%0, %1}, %2;" : "=f"(lo), "=f"(hi) : "l"(u))

// ---------------- scratch (device globals; no allocation allowed) ----------
__device__ float g_reduced[NPTS * 64];                  // 51 MB
__device__ float g_segsum[(size_t)NSEG_TOTAL * 64];     // 418 MB (touched-only init)
__device__ float g_segcnt[NSEG_TOTAL];
__device__ int   g_lin[NPTS * 4];
__device__ int   g_segidx[NSEG_TOTAL];                  // lin -> att slot (init -1)
__device__ int   g_seglist[4 * SEGCAP];                 // compact touched lists
__device__ int   g_cnt4[4];
__device__ int   g_pidx[NPTS * 4];                      // per (point,scale) att slot
__device__ float g_att[(size_t)4 * SEGCAP * 32];        // 103 MB
__device__ float g_proj[NPTS * 64];
__device__ float g_tv[(size_t)TVSEG * 64];              // 354 MB (touched-only init)
__device__ int   g_lin2[NPTS];
__device__ unsigned char g_flag[TVSEG];

// ---------------- k0a: thread per (point,scale): lin + claim ticket --------
__global__ void __launch_bounds__(256) k0a_claim(const int* __restrict__ coords)
{
    int idx = blockIdx.x * 256 + threadIdx.x;    // 800000 exactly
    int n = idx >> 2, j = idx & 3;

    int4 c = reinterpret_cast<const int4*>(coords)[n];
    int ps = (j == 0) ? 2 : (j == 1) ? 4 : (j == 2) ? 6 : 8;
    int dx = (j == 0) ? 240 : (j == 1) ? 120 : (j == 2) ? 80 : 60;
    int dy = (j == 0) ? 180 : (j == 1) ? 90 : (j == 2) ? 60 : 45;
    int dz = (j == 0) ? 16 : (j == 1) ? 8 : (j == 2) ? 6 : 4;
    int off = (j == 0) ? 0 : (j == 1) ? 1382400 : (j == 2) ? 1555200 : 1612800;

    int lin = ((c.x * dx + c.y / ps) * dy + c.z / ps) * dz + c.w / ps + off;
    g_lin[idx] = lin;

    if (atomicCAS(&g_segidx[lin], -1, 0x40000000) == -1) {
        int t = atomicAdd(&g_cnt4[j], 1);
        g_seglist[j * SEGCAP + t] = lin;
        g_segidx[lin] = j * SEGCAP + t;
    }
}

// ---------------- k0b: zero claimed segs + pidx resolve + tv sentinel ------
__global__ void __launch_bounds__(256) k0b_zero(const int* __restrict__ bxyz,
                                                float* __restrict__ out)
{
    int T = blockIdx.x * 256 + threadIdx.x;      // 8 threads per slot
    // side job 1: resolve g_pidx for k2_pt (removes its 2-hop load chain)
    if (T < NPTS * 4) g_pidx[T] = g_segidx[g_lin[T]];

    // side job 2 (former k3pre): sentinel-init touched tv segs, flags, lin2
    if (T < NPTS * 8) {
        int p = T >> 3, q = T & 7;
        int4 b = reinterpret_cast<const int4*>(bxyz)[p];
        int lin2 = ((b.x * 16 + b.w) * 180 + b.z) * 240 + b.y;
        uint4 s = make_uint4(0xFFFFFFFFu, 0xFFFFFFFFu, 0xFFFFFFFFu, 0xFFFFFFFFu);
        uint4* tv = reinterpret_cast<uint4*>(g_tv + (size_t)lin2 * 64);
        tv[2 * q]     = s;
        tv[2 * q + 1] = s;
        if (q == 0) {
            g_flag[lin2] = 1;
            g_lin2[p] = lin2;
            out[(size_t)NPTS * 64 + (size_t)TVSEG * 64 + p] = (float)lin2;
        }
    }

    int slot = T >> 3, q = T & 7;
    int j = slot / SEGCAP, i = slot - j * SEGCAP;
    if (i >= g_cnt4[j]) return;
    int lin = g_seglist[slot];
    float4 z4 = make_float4(0.f, 0.f, 0.f, 0.f);
    float4* dst = reinterpret_cast<float4*>(g_segsum + (size_t)lin * 64) + q * 2;
    dst[0] = z4;
    dst[1] = z4;
    if (q == 0) g_segcnt[lin] = 0.f;
}

// ---------------- k1: tile-staged reduce GEMM + warp-coop scatter ----------
// dyn smem floats: sW [64][64] 0..4096 | sb 4096..4160 | sx [256][65] 4160..
#define K1PAD 65
#define K1_SMEM ((4160 + 256 * K1PAD) * 4)
__global__ void __launch_bounds__(256, 2) k1_reduce(
    const float* __restrict__ input,
    const float* __restrict__ W_red, const float* __restrict__ b_red)
{
    extern __shared__ float s1[];
    float* sW = s1;
    float* sb = s1 + 4096;
    float* sx = s1 + 4160;
    const int tid = threadIdx.x;

    for (int i = tid; i < 4096; i += 256) sW[i] = W_red[i];
    if (tid < 64) sb[tid] = b_red[tid];

    const int pbase = blockIdx.x * 256;
    const float4* in4 = reinterpret_cast<const float4*>(input);
    #pragma unroll
    for (int i = 0; i < 16; ++i) {
        int e4 = i * 256 + tid;
        int pt = e4 >> 4, q = e4 & 15;
        if (pbase + pt < NPTS) {
            float4 v = in4[(size_t)(pbase + pt) * 16 + q];
            float* d = sx + pt * K1PAD + q * 4;
            d[0] = v.x; d[1] = v.y; d[2] = v.z; d[3] = v.w;
        }
    }
    __syncthreads();

    // GEMM: thread-per-point, f32x2 channel-packed, weights broadcast LDS
    {
        u64 acc[32];
        const u64* bp = reinterpret_cast<const u64*>(sb);
        #pragma unroll
        for (int i = 0; i < 32; ++i) acc[i] = bp[i];
        const ulonglong2* Wb = reinterpret_cast<const ulonglong2*>(sW);
        float* row = sx + tid * K1PAD;
        #pragma unroll 8
        for (int k = 0; k < 64; ++k) {
            u64 xp; PACK2(xp, row[k]);
            const ulonglong2* W = Wb + k * 16;
            #pragma unroll
            for (int i = 0; i < 16; ++i) {
                ulonglong2 wv = W[i];
                FFMA2(acc[2 * i],     xp, wv.x);
                FFMA2(acc[2 * i + 1], xp, wv.y);
            }
        }
        // relu + writeback to own row (x no longer needed)
        #pragma unroll
        for (int i = 0; i < 32; ++i) {
            float lo, hi; UNPK(lo, hi, acc[i]);
            row[2 * i]     = fmaxf(lo, 0.f);
            row[2 * i + 1] = fmaxf(hi, 0.f);
        }
    }
    __syncthreads();

    // warp-cooperative scatter: warp w handles points [pbase+w*32, +32)
    // NOTE: sx rows are at ODD float offsets (K1PAD=65) — scalar LDS only.
    const int wid = tid >> 5, lane = tid & 31;
    #pragma unroll 1
    for (int pp = 0; pp < 32; ++pp) {
        int pl = wid * 32 + pp;
        int p = pbase + pl;
        if (p >= NPTS) break;
        float v0 = sx[pl * K1PAD + 2 * lane];
        float v1 = sx[pl * K1PAD + 2 * lane + 1];
        reinterpret_cast<float2*>(g_reduced)[(size_t)p * 32 + lane]
            = make_float2(v0, v1);
        int4 L = reinterpret_cast<const int4*>(g_lin)[p];
        int lins[4] = {L.x, L.y, L.z, L.w};
        #pragma unroll
        for (int j = 0; j < 4; ++j) {
            float* addr = g_segsum + (size_t)lins[j] * 64 + 2 * lane;
            asm volatile("red.global.add.v2.f32 [%0], {%1, %2};"
                         :: "l"(addr), "f"(v0), "f"(v1) : "memory");
            if (lane == 0) atomicAdd(&g_segcnt[lins[j]], 1.0f);
        }
    }
}

// ---------------- k2_seg: per touched segment, att = relu(mean @ flW + b) --
// direct gmem loads (measured best); per-scale weights only (8 KB)
__global__ void __launch_bounds__(256) k2_seg(
    const float* __restrict__ flW, const float* __restrict__ flb)
{
    __shared__ __align__(16) float sW[2048];
    __shared__ __align__(16) float sb[32];
    const int tid = threadIdx.x;
    const int j = blockIdx.x / 784;
    const int base = (blockIdx.x % 784) * 256;

    for (int i = tid; i < 2048; i += 256) sW[i] = flW[j * 2048 + i];
    if (tid < 32) sb[tid] = flb[j * 32 + tid];
    __syncthreads();

    const int i = base + tid;
    if (i >= g_cnt4[j]) return;
    const int lin = g_seglist[j * SEGCAP + i];

    float inv = 1.f / fmaxf(g_segcnt[lin], 1.f);

    u64 acc[16];
    {
        const u64* bp = reinterpret_cast<const u64*>(sb);
        #pragma unroll
        for (int q = 0; q < 16; ++q) acc[q] = bp[q];
    }
    const ulonglong2* Wb = reinterpret_cast<const ulonglong2*>(sW);
    const float4* src = reinterpret_cast<const float4*>(g_segsum + (size_t)lin * 64);

    #pragma unroll 1
    for (int kc = 0; kc < 4; ++kc) {
        float4 fk4[4];
        #pragma unroll
        for (int q = 0; q < 4; ++q) fk4[q] = __ldcs(&src[kc * 4 + q]);
        #pragma unroll
        for (int k = 0; k < 16; ++k) {
            float4 v = fk4[k >> 2];
            float xs = ((k & 3) == 0) ? v.x : ((k & 3) == 1) ? v.y
                       : ((k & 3) == 2) ? v.z : v.w;
            xs *= inv;
            u64 xp; PACK2(xp, xs);
            const ulonglong2* W = Wb + (kc * 16 + k) * 8;
            #pragma unroll
            for (int q = 0; q < 8; ++q) {
                ulonglong2 wv = W[q];
                FFMA2(acc[2 * q],     xp, wv.x);
                FFMA2(acc[2 * q + 1], xp, wv.y);
            }
        }
    }
    float4* dst = reinterpret_cast<float4*>(g_att + (size_t)(j * SEGCAP + i) * 32);
    #pragma unroll
    for (int q = 0; q < 8; ++q) {
        float l0, h0, l1, h1;
        UNPK(l0, h0, acc[2 * q]);
        UNPK(l1, h1, acc[2 * q + 1]);
        dst[q] = make_float4(fmaxf(l0, 0.f), fmaxf(h0, 0.f),
                             fmaxf(l1, 0.f), fmaxf(h1, 0.f));
    }
}

// ---------------- k2_pt: per-point chain, f32x2 channel-packed -------------
#define K2T 256
// SMEM float offsets:
#define OFFP_FCW   0        // [32][32]     1024
#define OFFP_FCSW  1024     // [4][32][32]  4096
#define OFFP_FCSB  5120     // 128
#define OFFP_OUTW  5248     // [32][64]     2048
#define OFFP_LO1   7296     // [128][64]    8192
#define OFFP_LO2   15488    // [64][64]     4096
#define OFFP_LOB   19584    // 64
#define OFFP_X     19648    // scratch [32][256]  8192
#define K2PT_SMEM ((19648 + 32 * K2T) * 4)

__global__ void __launch_bounds__(K2T, 2) k2_pt(
    const float* __restrict__ fcW, const float* __restrict__ fcsW,
    const float* __restrict__ fcsb, const float* __restrict__ outW,
    const float* __restrict__ lo1, const float* __restrict__ lo2,
    const float* __restrict__ lob)
{
    extern __shared__ float sm[];
    const int tid = threadIdx.x;

    for (int i = tid; i < 1024; i += K2T) sm[OFFP_FCW + i]  = fcW[i];
    for (int i = tid; i < 4096; i += K2T) sm[OFFP_FCSW + i] = fcsW[i];
    for (int i = tid; i < 128;  i += K2T) sm[OFFP_FCSB + i] = fcsb[i];
    for (int i = tid; i < 2048; i += K2T) sm[OFFP_OUTW + i] = outW[i];
    for (int i = tid; i < 8192; i += K2T) sm[OFFP_LO1 + i]  = lo1[i];
    for (int i = tid; i < 4096; i += K2T) sm[OFFP_LO2 + i]  = lo2[i];
    if (tid < 64) sm[OFFP_LOB + tid] = lob[tid];
    __syncthreads();

    const int n = blockIdx.x * K2T + tid;
    if (n >= NPTS) return;
    float* s_x = sm + OFFP_X;

    int4 pid = *reinterpret_cast<const int4*>(g_pidx + n * 4);
    int idx4[4] = {pid.x, pid.y, pid.z, pid.w};

    // ===== P1: featS = sum_j att_j (regs) =================================
    float featS[32];
    #pragma unroll
    for (int c = 0; c < 32; ++c) featS[c] = 0.f;
    #pragma unroll 2
    for (int j = 0; j < 4; ++j) {
        const float4* sf = reinterpret_cast<const float4*>(
            g_att + (size_t)idx4[j] * 32);
        #pragma unroll
        for (int i = 0; i < 8; ++i) {
            float4 v = sf[i];
            featS[4 * i + 0] += v.x; featS[4 * i + 1] += v.y;
            featS[4 * i + 2] += v.z; featS[4 * i + 3] += v.w;
        }
    }

    // ===== P2: z = relu(featS @ fcW), z kept packed (u64 pairs) ===========
    u64 zp[16];
    {
        #pragma unroll
        for (int i = 0; i < 16; ++i) zp[i] = 0ull;
        const ulonglong2* Wf = reinterpret_cast<const ulonglong2*>(sm + OFFP_FCW);
        #pragma unroll
        for (int k = 0; k < 32; ++k) {
            u64 xp; PACK2(xp, featS[k]);
            const ulonglong2* W = Wf + k * 8;
            #pragma unroll
            for (int i = 0; i < 8; ++i) {
                ulonglong2 wv = W[i];
                FFMA2(zp[2 * i],     xp, wv.x);
                FFMA2(zp[2 * i + 1], xp, wv.y);
            }
        }
        #pragma unroll
        for (int i = 0; i < 16; ++i) {
            float lo, hi; UNPK(lo, hi, zp[i]);
            lo = fmaxf(lo, 0.f); hi = fmaxf(hi, 0.f);
            PACKLH(zp[i], lo, hi);
        }
    }

    // ===== P3: fp = sum_j att_j * sigmoid(z @ fcsW_j + fcsb_j) ============
    float fp[32];
    #pragma unroll
    for (int c = 0; c < 32; ++c) fp[c] = 0.f;
    #pragma unroll 1
    for (int j = 0; j < 4; ++j) {
        u64 acc[16];
        {
            const u64* bp = reinterpret_cast<const u64*>(sm + OFFP_FCSB + j * 32);
            #pragma unroll
            for (int i = 0; i < 16; ++i) acc[i] = bp[i];
        }
        const ulonglong2* Wj = reinterpret_cast<const ulonglong2*>(sm + OFFP_FCSW)
                               + (size_t)j * 32 * 8;
        #pragma unroll
        for (int kp = 0; kp < 16; ++kp) {
            float zl, zh; UNPK(zl, zh, zp[kp]);
            u64 xp0; PACK2(xp0, zl);
            const ulonglong2* W = Wj + (2 * kp) * 8;
            #pragma unroll
            for (int i = 0; i < 8; ++i) {
                ulonglong2 wv = W[i];
                FFMA2(acc[2 * i],     xp0, wv.x);
                FFMA2(acc[2 * i + 1], xp0, wv.y);
            }
            u64 xp1; PACK2(xp1, zh);
            W = Wj + (2 * kp + 1) * 8;
            #pragma unroll
            for (int i = 0; i < 8; ++i) {
                ulonglong2 wv = W[i];
                FFMA2(acc[2 * i],     xp1, wv.x);
                FFMA2(acc[2 * i + 1], xp1, wv.y);
            }
        }
        const float4* sfsrc = reinterpret_cast<const float4*>(
            g_att + (size_t)idx4[j] * 32);
        #pragma unroll
        for (int i = 0; i < 8; ++i) {
            float4 sv = sfsrc[i];
            float l0, h0, l1, h1;
            UNPK(l0, h0, acc[2 * i]);
            UNPK(l1, h1, acc[2 * i + 1]);
            float a0 = __fdividef(1.f, 1.f + __expf(-l0));
            float a1 = __fdividef(1.f, 1.f + __expf(-h0));
            float a2 = __fdividef(1.f, 1.f + __expf(-l1));
            float a3 = __fdividef(1.f, 1.f + __expf(-h1));
            fp[4 * i + 0] = fmaf(sv.x, a0, fp[4 * i + 0]);
            fp[4 * i + 1] = fmaf(sv.y, a1, fp[4 * i + 1]);
            fp[4 * i + 2] = fmaf(sv.z, a2, fp[4 * i + 2]);
            fp[4 * i + 3] = fmaf(sv.w, a3, fp[4 * i + 3]);
        }
    }

    // ===== P4: fused = fp @ outW (packed); low half -> scratch ============
    u64 facc[32];
    {
        #pragma unroll
        for (int i = 0; i < 32; ++i) facc[i] = 0ull;
        const ulonglong2* Wo = reinterpret_cast<const ulonglong2*>(sm + OFFP_OUTW);
        #pragma unroll
        for (int k = 0; k < 32; ++k) {
            u64 xp; PACK2(xp, fp[k]);
            const ulonglong2* W = Wo + k * 16;
            #pragma unroll
            for (int i = 0; i < 16; ++i) {
                ulonglong2 wv = W[i];
                FFMA2(facc[2 * i],     xp, wv.x);
                FFMA2(facc[2 * i + 1], xp, wv.y);
            }
        }
        // stage fused channels 0..31 (facc[0..15]) to scratch rows 0..31
        #pragma unroll
        for (int i = 0; i < 16; ++i) {
            float lo, hi; UNPK(lo, hi, facc[i]);
            s_x[(2 * i) * K2T + tid]     = lo;
            s_x[(2 * i + 1) * K2T + tid] = hi;
        }
    }

    // ===== P5: h = relu([reduced, fused] @ lo1) (packed accs) =============
    float h[64];
    {
        u64 hacc[32];
        #pragma unroll
        for (int i = 0; i < 32; ++i) hacc[i] = 0ull;
        const ulonglong2* Wl = reinterpret_cast<const ulonglong2*>(sm + OFFP_LO1);
        const float4* rsrc = reinterpret_cast<const float4*>(
            g_reduced + (size_t)n * 64);
        // (a) reduced, k = 0..63  (unroll 2 -> 2 float4 loads in flight)
        #pragma unroll 2
        for (int k4 = 0; k4 < 16; ++k4) {
            float4 r = rsrc[k4];
            #pragma unroll
            for (int kk = 0; kk < 4; ++kk) {
                float xs = (kk == 0) ? r.x : (kk == 1) ? r.y : (kk == 2) ? r.z : r.w;
                u64 xp; PACK2(xp, xs);
                const ulonglong2* W = Wl + (k4 * 4 + kk) * 16;
                #pragma unroll
                for (int i = 0; i < 16; ++i) {
                    ulonglong2 wv = W[i];
                    FFMA2(hacc[2 * i],     xp, wv.x);
                    FFMA2(hacc[2 * i + 1], xp, wv.y);
                }
            }
        }
        // (b) fused low from scratch, k = 64..95
        #pragma unroll 2
        for (int k = 0; k < 32; ++k) {
            float xs = s_x[k * K2T + tid];
            u64 xp; PACK2(xp, xs);
            const ulonglong2* W = Wl + (64 + k) * 16;
            #pragma unroll
            for (int i = 0; i < 16; ++i) {
                ulonglong2 wv = W[i];
                FFMA2(hacc[2 * i],     xp, wv.x);
                FFMA2(hacc[2 * i + 1], xp, wv.y);
            }
        }
        // (c) fused high from regs, k = 96..127
        #pragma unroll
        for (int kp = 0; kp < 16; ++kp) {
            float f0, f1; UNPK(f0, f1, facc[16 + kp]);
            u64 xp0; PACK2(xp0, f0);
            const ulonglong2* W = Wl + (96 + 2 * kp) * 16;
            #pragma unroll
            for (int i = 0; i < 16; ++i) {
                ulonglong2 wv = W[i];
                FFMA2(hacc[2 * i],     xp0, wv.x);
                FFMA2(hacc[2 * i + 1], xp0, wv.y);
            }
            u64 xp1; PACK2(xp1, f1);
            W = Wl + (96 + 2 * kp + 1) * 16;
            #pragma unroll
            for (int i = 0; i < 16; ++i) {
                ulonglong2 wv = W[i];
                FFMA2(hacc[2 * i],     xp1, wv.x);
                FFMA2(hacc[2 * i + 1], xp1, wv.y);
            }
        }
        #pragma unroll
        for (int i = 0; i < 32; ++i) {
            float lo, hi; UNPK(lo, hi, hacc[i]);
            h[2 * i]     = fmaxf(lo, 0.f);
            h[2 * i + 1] = fmaxf(hi, 0.f);
        }
    }

    // ===== P6: proj = h @ lo2 + lob, in two 32-ch halves ==================
    float4* pdst = reinterpret_cast<float4*>(g_proj + (size_t)n * 64);
    const ulonglong2* W2 = reinterpret_cast<const ulonglong2*>(sm + OFFP_LO2);
    #pragma unroll 1
    for (int s = 0; s < 2; ++s) {
        u64 pa[16];
        {
            const u64* bp = reinterpret_cast<const u64*>(sm + OFFP_LOB) + s * 16;
            #pragma unroll
            for (int i = 0; i < 16; ++i) pa[i] = bp[i];
        }
        #pragma unroll
        for (int k = 0; k < 64; ++k) {
            u64 xp; PACK2(xp, h[k]);
            const ulonglong2* W = W2 + k * 16 + s * 8;
            #pragma unroll
            for (int i = 0; i < 8; ++i) {
                ulonglong2 wv = W[i];
                FFMA2(pa[2 * i],     xp, wv.x);
                FFMA2(pa[2 * i + 1], xp, wv.y);
            }
        }
        #pragma unroll
        for (int q = 0; q < 8; ++q) {
            float l0, h0, l1, h1;
            UNPK(l0, h0, pa[2 * q]);
            UNPK(l1, h1, pa[2 * q + 1]);
            pdst[s * 8 + q] = make_float4(l0, h0, l1, h1);
        }
    }
}

// ---------------- k3: gather by inv + atomic segment-max -------------------
__device__ __forceinline__ void atomicMaxFloat(float* addr, float v)
{
    if (v >= 0.f) atomicMax((int*)addr, __float_as_int(v));
    else          atomicMin((unsigned int*)addr, __float_as_uint(v));
}

__global__ void __launch_bounds__(256) k3_scatter(const int* __restrict__ inv,
                                                  float* __restrict__ out)
{
    int idx = blockIdx.x * 256 + threadIdx.x;
    int n = idx >> 6, c = idx & 63;
    int src = inv[n];
    float v = g_proj[src * 64 + c];
    __stcs(&out[idx], v);                // streaming: out not re-read
    int lin2 = g_lin2[n];
    atomicMaxFloat(&g_tv[(size_t)lin2 * 64 + c], v);
}

// ---------------- k4: finalize tv -> out (flag-gated) ----------------------
__global__ void __launch_bounds__(256) k4_final(float* __restrict__ out)
{
    size_t idx = (size_t)blockIdx.x * 256 + threadIdx.x;   // float4 units
    size_t seg = idx >> 4;
    float4 v = make_float4(0.f, 0.f, 0.f, 0.f);
    if (g_flag[seg])
        v = __ldcs(reinterpret_cast<const float4*>(g_tv) + idx);
    __stcs(reinterpret_cast<float4*>(out + (size_t)NPTS * 64) + idx, v);
}

// ---------------- launch ---------------------------------------------------
extern "C" void kernel_launch(void* const* d_in, const int* in_sizes, int n_in,
                              void* d_out, int out_size)
{
    const float* input     = (const float*)d_in[0];
    const int*   coords    = (const int*)  d_in[1];
    const int*   inv       = (const int*)  d_in[2];
    const int*   bxyz      = (const int*)  d_in[3];
    const float* W_red     = (const float*)d_in[4];
    const float* b_red     = (const float*)d_in[5];
    const float* fc_list_W = (const float*)d_in[6];
    const float* fc_list_b = (const float*)d_in[7];
    const float* fcs_W     = (const float*)d_in[8];
    const float* fcs_b     = (const float*)d_in[9];
    const float* fc_W      = (const float*)d_in[10];
    const float* out_fc_W  = (const float*)d_in[11];
    const float* lo_W1     = (const float*)d_in[12];
    const float* lo_W2     = (const float*)d_in[13];
    const float* lo_b2     = (const float*)d_in[14];
    float* out = (float*)d_out;

    void* p;
    cudaGetSymbolAddress(&p, g_flag);
    cudaMemsetAsync(p, 0, TVSEG);
    cudaGetSymbolAddress(&p, g_segidx);
    cudaMemsetAsync(p, 0xFF, NSEG_TOTAL * sizeof(int));   // -1
    cudaGetSymbolAddress(&p, g_cnt4);
    cudaMemsetAsync(p, 0, 4 * sizeof(int));

    cudaFuncSetAttribute(k1_reduce, cudaFuncAttributeMaxDynamicSharedMemorySize,
                         K1_SMEM);
    cudaFuncSetAttribute(k2_pt, cudaFuncAttributeMaxDynamicSharedMemorySize,
                         K2PT_SMEM);

    k0a_claim<<<3125, 256>>>(coords);                       // 800k threads
    k0b_zero<<<(4 * SEGCAP * 8) / 256, 256>>>(bxyz, out);   // zero + pidx + tv
    k1_reduce<<<782, 256, K1_SMEM>>>(input, W_red, b_red);
    k2_seg<<<4 * 784, 256>>>(fc_list_W, fc_list_b);
    k2_pt<<<(NPTS + K2T - 1) / K2T, K2T, K2PT_SMEM>>>(fc_W, fcs_W, fcs_b,
                                                      out_fc_W, lo_W1, lo_W2,
                                                      lo_b2);
    k3_scatter<<<50000, 256>>>(inv, out);
    k4_final<<<86400, 256>>>(out);
}